// round 9
// baseline (speedup 1.0000x reference)
#include <cuda_runtime.h>
#include <cuda_bf16.h>
#include <cstdint>

#define B_ROWS 8192
#define DFEAT  512
#define KOUT   1024

// Scratch (__device__ globals; no dynamic allocation allowed)
__device__ __align__(16) __nv_bfloat16 g_xb[B_ROWS * DFEAT];   // 8 MB
__device__ __align__(16) __nv_bfloat16 g_wb[KOUT * DFEAT];     // 1 MB
__device__ float g_xsq[B_ROWS];
__device__ float g_wsq[KOUT];

// ---------------------------------------------------------------------------
// Kernel 1: convert x,w to bf16 + row squared norms. 2 rows per warp (MLP 8).
// ---------------------------------------------------------------------------
__global__ void prep_kernel(const float* __restrict__ x, const float* __restrict__ w) {
    int gw   = (blockIdx.x * blockDim.x + threadIdx.x) >> 5;
    int lane = threadIdx.x & 31;
    int r0 = gw * 2;

    const float* src[2];
    __nv_bfloat16* dst[2];
    float* sqp[2];
    int sqi[2];
#pragma unroll
    for (int j = 0; j < 2; j++) {
        int r = r0 + j;
        if (r < B_ROWS) {
            src[j] = x + (size_t)r * DFEAT;
            dst[j] = g_xb + (size_t)r * DFEAT;
            sqp[j] = g_xsq; sqi[j] = r;
        } else {
            int rr = r - B_ROWS;
            src[j] = w + (size_t)rr * DFEAT;
            dst[j] = g_wb + (size_t)rr * DFEAT;
            sqp[j] = g_wsq; sqi[j] = rr;
        }
    }

    float4 v[2][4];
#pragma unroll
    for (int j = 0; j < 2; j++)
#pragma unroll
        for (int i = 0; i < 4; i++)
            v[j][i] = *reinterpret_cast<const float4*>(src[j] + i * 128 + lane * 4);

#pragma unroll
    for (int j = 0; j < 2; j++) {
        float s = 0.0f;
#pragma unroll
        for (int i = 0; i < 4; i++) {
            float4 q = v[j][i];
            s += q.x * q.x + q.y * q.y + q.z * q.z + q.w * q.w;
            __nv_bfloat162 p0 = __float22bfloat162_rn(make_float2(q.x, q.y));
            __nv_bfloat162 p1 = __float22bfloat162_rn(make_float2(q.z, q.w));
            uint2 pk;
            pk.x = *reinterpret_cast<uint32_t*>(&p0);
            pk.y = *reinterpret_cast<uint32_t*>(&p1);
            *reinterpret_cast<uint2*>(dst[j] + i * 128 + lane * 4) = pk;
        }
#pragma unroll
        for (int off = 16; off >= 1; off >>= 1)
            s += __shfl_xor_sync(0xFFFFFFFFu, s, off);
        if (lane == 0) sqp[j][sqi[j]] = s;
    }
}

// ---------------------------------------------------------------------------
// Kernel 2: bf16 mma.sync GEMM with 3-stage cp.async pipeline.
// CTA tile 128(M) x 128(N), KC=64. 8 warps = 4(M) x 2(N), warp 32x64,
// 64 fp32 accum regs/thread. Fused epilogue q_un = 1/(1+max(dist,0)).
// ---------------------------------------------------------------------------
#define ST_PITCH   72                 // elements: 64 + 8 padding (144 B rows)
#define TILE_BYTES (128 * ST_PITCH * 2)   // 18432 B (one A or B tile)
#define STAGE_BYTES (2 * TILE_BYTES)      // A + B = 36864 B
#define NSTAGE 3
#define OFF_SQ (NSTAGE * STAGE_BYTES)     // 110592
#define GEMM_SMEM (OFF_SQ + 1024)         // +sXsq[128]+sWsq[128]

__device__ __forceinline__ void ldmatrix_x4(uint32_t& r0, uint32_t& r1,
                                            uint32_t& r2, uint32_t& r3,
                                            uint32_t saddr) {
    asm volatile("ldmatrix.sync.aligned.m8n8.x4.shared.b16 {%0,%1,%2,%3}, [%4];"
                 : "=r"(r0), "=r"(r1), "=r"(r2), "=r"(r3) : "r"(saddr));
}

__device__ __forceinline__ void mma_bf16(float* d, const uint32_t* a,
                                         uint32_t b0, uint32_t b1) {
    asm volatile(
        "mma.sync.aligned.m16n8k16.row.col.f32.bf16.bf16.f32 "
        "{%0,%1,%2,%3}, {%4,%5,%6,%7}, {%8,%9}, {%0,%1,%2,%3};"
        : "+f"(d[0]), "+f"(d[1]), "+f"(d[2]), "+f"(d[3])
        : "r"(a[0]), "r"(a[1]), "r"(a[2]), "r"(a[3]), "r"(b0), "r"(b1));
}

__device__ __forceinline__ void cp16(uint32_t s, const void* g) {
    asm volatile("cp.async.cg.shared.global [%0], [%1], 16;" :: "r"(s), "l"(g));
}

// Load one KC=64 stage of A (128 rows from g_xb) and B (128 rows from g_wb).
// Tile row = 128 bytes = 8 chunks of 16 B -> row = idx>>3, cb = (idx&7)<<4.
__device__ __forceinline__ void load_stage(uint32_t sbase, int stage, int kc,
                                           int m0, int n0, int tid) {
    const char* gA = (const char*)g_xb + (size_t)m0 * 1024 + (size_t)kc * 128;
    const char* gB = (const char*)g_wb + (size_t)n0 * 1024 + (size_t)kc * 128;
    uint32_t aB = sbase + stage * STAGE_BYTES;
    uint32_t bB = aB + TILE_BYTES;
#pragma unroll
    for (int i = 0; i < 4; i++) {
        int idx = tid + i * 256;          // 1024 16B-chunks per tile
        int row = idx >> 3;               // 0..127
        int cb  = (idx & 7) << 4;         // 0..112
        cp16(aB + row * 144 + cb, gA + (size_t)row * 1024 + cb);
        cp16(bB + row * 144 + cb, gB + (size_t)row * 1024 + cb);
    }
}

__global__ __launch_bounds__(256) void gemm_kernel(float* __restrict__ out) {
    extern __shared__ __align__(16) char smem[];
    uint32_t sbase;
    asm("{ .reg .u64 t; cvta.to.shared.u64 t, %1; cvt.u32.u64 %0, t; }"
        : "=r"(sbase) : "l"(smem));

    const int tid  = threadIdx.x;
    const int lane = tid & 31;
    const int warp = tid >> 5;
    const int wm = warp & 3;   // 4 warps in M
    const int wn = warp >> 2;  // 2 warps in N
    const int m0 = blockIdx.y * 128;
    const int n0 = blockIdx.x * 128;

    float* sXsq = reinterpret_cast<float*>(smem + OFF_SQ);
    float* sWsq = sXsq + 128;
    if (tid < 128) {
        sXsq[tid] = g_xsq[m0 + tid];
        sWsq[tid] = g_wsq[n0 + tid];
    }

    float acc[2][8][4];
#pragma unroll
    for (int mi = 0; mi < 2; mi++)
#pragma unroll
        for (int ni = 0; ni < 8; ni++)
#pragma unroll
            for (int e = 0; e < 4; e++) acc[mi][ni][e] = 0.0f;

    // lane-dependent ldmatrix address parts
    const int a_row = (lane & 15);
    const int a_cg  = (lane >> 4) << 3;
    const int b_r   = lane & 7;
    const int b_sel = lane >> 3;
    const int b_nof = ((b_sel >> 1) << 3) + b_r;
    const int b_kof = (b_sel & 1) << 3;

    // Prologue: stages 0 and 1 in flight
    load_stage(sbase, 0, 0, m0, n0, tid);
    asm volatile("cp.async.commit_group;" ::: "memory");
    load_stage(sbase, 1, 1, m0, n0, tid);
    asm volatile("cp.async.commit_group;" ::: "memory");

#pragma unroll 1
    for (int kc = 0; kc < 8; kc++) {
        const int st = kc % NSTAGE;
        if (kc < 7) asm volatile("cp.async.wait_group 1;" ::: "memory");
        else        asm volatile("cp.async.wait_group 0;" ::: "memory");
        __syncthreads();

        // issue loads for kc+2 into buffer (kc+2)%3 (last read at iter kc-1)
        if (kc + 2 < 8) {
            load_stage(sbase, (kc + 2) % NSTAGE, kc + 2, m0, n0, tid);
            asm volatile("cp.async.commit_group;" ::: "memory");
        }

        uint32_t aBase = sbase + st * STAGE_BYTES;
        uint32_t bBase = aBase + TILE_BYTES;

#pragma unroll
        for (int ks = 0; ks < 64; ks += 16) {
            uint32_t af[2][4];
#pragma unroll
            for (int mi = 0; mi < 2; mi++) {
                int r = wm * 32 + mi * 16 + a_row;
                int c = ks + a_cg;
                ldmatrix_x4(af[mi][0], af[mi][1], af[mi][2], af[mi][3],
                            aBase + r * 144 + c * 2);
            }
            uint32_t bfr[4][4];
#pragma unroll
            for (int j = 0; j < 4; j++) {
                int n = wn * 64 + j * 16 + b_nof;
                int c = ks + b_kof;
                ldmatrix_x4(bfr[j][0], bfr[j][1], bfr[j][2], bfr[j][3],
                            bBase + n * 144 + c * 2);
            }
#pragma unroll
            for (int mi = 0; mi < 2; mi++)
#pragma unroll
                for (int ni = 0; ni < 8; ni++) {
                    int j = ni >> 1, h = (ni & 1) * 2;
                    mma_bf16(acc[mi][ni], af[mi], bfr[j][h], bfr[j][h + 1]);
                }
        }
    }

    // Fused epilogue: q_un = 1/(1+max(dist,0))
    const int qt = lane >> 2;
    const int qr = lane & 3;
#pragma unroll
    for (int mi = 0; mi < 2; mi++) {
        int lr = wm * 32 + mi * 16 + qt;
        float xs0 = sXsq[lr];
        float xs1 = sXsq[lr + 8];
        int gr0 = (m0 + lr) * KOUT;
        int gr1 = gr0 + 8 * KOUT;
#pragma unroll
        for (int ni = 0; ni < 8; ni++) {
            int nl = wn * 64 + ni * 8 + qr * 2;
            float w0 = sWsq[nl];
            float w1 = sWsq[nl + 1];
            const float* d = acc[mi][ni];
            float q00 = 1.0f / (1.0f + fmaxf(xs0 + w0 - 2.0f * d[0], 0.0f));
            float q01 = 1.0f / (1.0f + fmaxf(xs0 + w1 - 2.0f * d[1], 0.0f));
            float q10 = 1.0f / (1.0f + fmaxf(xs1 + w0 - 2.0f * d[2], 0.0f));
            float q11 = 1.0f / (1.0f + fmaxf(xs1 + w1 - 2.0f * d[3], 0.0f));
            *reinterpret_cast<float2*>(&out[gr0 + n0 + nl]) = make_float2(q00, q01);
            *reinterpret_cast<float2*>(&out[gr1 + n0 + nl]) = make_float2(q10, q11);
        }
    }
}

// ---------------------------------------------------------------------------
// Kernel 3: deterministic row normalization (warp per row, L2-hot readback).
// ---------------------------------------------------------------------------
__global__ void norm_kernel(float* __restrict__ out) {
    int warp = threadIdx.x >> 5;
    int lane = threadIdx.x & 31;
    int row  = blockIdx.x * 8 + warp;
    float* p = out + (size_t)row * KOUT;

    float4 v[8];
    float s = 0.0f;
#pragma unroll
    for (int i = 0; i < 8; i++) {
        v[i] = *reinterpret_cast<float4*>(&p[i * 128 + lane * 4]);
        s += v[i].x + v[i].y + v[i].z + v[i].w;
    }
#pragma unroll
    for (int off = 16; off >= 1; off >>= 1)
        s += __shfl_xor_sync(0xFFFFFFFFu, s, off);
    float inv = 1.0f / s;
#pragma unroll
    for (int i = 0; i < 8; i++) {
        v[i].x *= inv; v[i].y *= inv; v[i].z *= inv; v[i].w *= inv;
        *reinterpret_cast<float4*>(&p[i * 128 + lane * 4]) = v[i];
    }
}

// ---------------------------------------------------------------------------
extern "C" void kernel_launch(void* const* d_in, const int* in_sizes, int n_in,
                              void* d_out, int out_size) {
    const float* x = (const float*)d_in[0];   // [8192, 512] f32
    const float* w = (const float*)d_in[1];   // [1024, 512] f32
    float* out = (float*)d_out;               // [8192, 1024] f32

    cudaFuncSetAttribute(gemm_kernel, cudaFuncAttributeMaxDynamicSharedMemorySize,
                         GEMM_SMEM);

    prep_kernel<<<576, 256>>>(x, w);
    gemm_kernel<<<dim3(KOUT / 128, B_ROWS / 128), 256, GEMM_SMEM>>>(out);
    norm_kernel<<<B_ROWS / 8, 256>>>(out);
}

// round 10
// speedup vs baseline: 1.0137x; 1.0137x over previous
#include <cuda_runtime.h>
#include <cuda_bf16.h>
#include <cstdint>

#define B_ROWS 8192
#define DFEAT  512
#define KOUT   1024

// Scratch (__device__ globals; no dynamic allocation allowed)
__device__ __align__(16) __nv_bfloat16 g_xb[B_ROWS * DFEAT];   // 8 MB
__device__ __align__(16) __nv_bfloat16 g_wb[KOUT * DFEAT];     // 1 MB
__device__ float g_xsq[B_ROWS];
__device__ float g_wsq[KOUT];

// ---------------------------------------------------------------------------
// Kernel 1: convert x,w to bf16 + row squared norms. 4 rows per warp (MLP 16).
// 9216 rows / 4 = 2304 warps; x/w boundary (8192) is 4-aligned so no straddle.
// ---------------------------------------------------------------------------
__global__ void prep_kernel(const float* __restrict__ x, const float* __restrict__ w) {
    int gw   = (blockIdx.x * blockDim.x + threadIdx.x) >> 5;
    int lane = threadIdx.x & 31;
    int r0 = gw * 4;

    const float* src[4];
    __nv_bfloat16* dst[4];
    float* sqp[4];
    int sqi[4];
#pragma unroll
    for (int j = 0; j < 4; j++) {
        int r = r0 + j;
        if (r < B_ROWS) {
            src[j] = x + (size_t)r * DFEAT;
            dst[j] = g_xb + (size_t)r * DFEAT;
            sqp[j] = g_xsq; sqi[j] = r;
        } else {
            int rr = r - B_ROWS;
            src[j] = w + (size_t)rr * DFEAT;
            dst[j] = g_wb + (size_t)rr * DFEAT;
            sqp[j] = g_wsq; sqi[j] = rr;
        }
    }

    float4 v[4][4];
#pragma unroll
    for (int j = 0; j < 4; j++)
#pragma unroll
        for (int i = 0; i < 4; i++)
            v[j][i] = *reinterpret_cast<const float4*>(src[j] + i * 128 + lane * 4);

#pragma unroll
    for (int j = 0; j < 4; j++) {
        float s = 0.0f;
#pragma unroll
        for (int i = 0; i < 4; i++) {
            float4 q = v[j][i];
            s += q.x * q.x + q.y * q.y + q.z * q.z + q.w * q.w;
            __nv_bfloat162 p0 = __float22bfloat162_rn(make_float2(q.x, q.y));
            __nv_bfloat162 p1 = __float22bfloat162_rn(make_float2(q.z, q.w));
            uint2 pk;
            pk.x = *reinterpret_cast<uint32_t*>(&p0);
            pk.y = *reinterpret_cast<uint32_t*>(&p1);
            *reinterpret_cast<uint2*>(dst[j] + i * 128 + lane * 4) = pk;
        }
#pragma unroll
        for (int off = 16; off >= 1; off >>= 1)
            s += __shfl_xor_sync(0xFFFFFFFFu, s, off);
        if (lane == 0) sqp[j][sqi[j]] = s;
    }
}

// ---------------------------------------------------------------------------
// Kernel 2: bf16 mma.sync GEMM with 3-stage cp.async pipeline, 2 CTAs/SM.
// CTA tile 128(M) x 128(N), KC=64. 8 warps = 4(M) x 2(N), warp 32x64,
// 64 fp32 accum regs/thread. Fused epilogue q_un = 1/(1+max(dist,0)).
// ---------------------------------------------------------------------------
#define ST_PITCH   72                 // elements: 64 + 8 padding (144 B rows)
#define TILE_BYTES (128 * ST_PITCH * 2)   // 18432 B (one A or B tile)
#define STAGE_BYTES (2 * TILE_BYTES)      // A + B = 36864 B
#define NSTAGE 3
#define OFF_SQ (NSTAGE * STAGE_BYTES)     // 110592
#define GEMM_SMEM (OFF_SQ + 1024)         // 111616 B -> 2 CTAs/SM = 223232 <= 228KB

__device__ __forceinline__ void ldmatrix_x4(uint32_t& r0, uint32_t& r1,
                                            uint32_t& r2, uint32_t& r3,
                                            uint32_t saddr) {
    asm volatile("ldmatrix.sync.aligned.m8n8.x4.shared.b16 {%0,%1,%2,%3}, [%4];"
                 : "=r"(r0), "=r"(r1), "=r"(r2), "=r"(r3) : "r"(saddr));
}

__device__ __forceinline__ void mma_bf16(float* d, const uint32_t* a,
                                         uint32_t b0, uint32_t b1) {
    asm volatile(
        "mma.sync.aligned.m16n8k16.row.col.f32.bf16.bf16.f32 "
        "{%0,%1,%2,%3}, {%4,%5,%6,%7}, {%8,%9}, {%0,%1,%2,%3};"
        : "+f"(d[0]), "+f"(d[1]), "+f"(d[2]), "+f"(d[3])
        : "r"(a[0]), "r"(a[1]), "r"(a[2]), "r"(a[3]), "r"(b0), "r"(b1));
}

__device__ __forceinline__ void cp16(uint32_t s, const void* g) {
    asm volatile("cp.async.cg.shared.global [%0], [%1], 16;" :: "r"(s), "l"(g));
}

// Load one KC=64 stage of A (128 rows from g_xb) and B (128 rows from g_wb).
// Tile row = 128 bytes = 8 chunks of 16 B -> row = idx>>3, cb = (idx&7)<<4.
__device__ __forceinline__ void load_stage(uint32_t sbase, int stage, int kc,
                                           int m0, int n0, int tid) {
    const char* gA = (const char*)g_xb + (size_t)m0 * 1024 + (size_t)kc * 128;
    const char* gB = (const char*)g_wb + (size_t)n0 * 1024 + (size_t)kc * 128;
    uint32_t aB = sbase + stage * STAGE_BYTES;
    uint32_t bB = aB + TILE_BYTES;
#pragma unroll
    for (int i = 0; i < 4; i++) {
        int idx = tid + i * 256;          // 1024 16B-chunks per tile
        int row = idx >> 3;               // 0..127
        int cb  = (idx & 7) << 4;         // 0..112
        cp16(aB + row * 144 + cb, gA + (size_t)row * 1024 + cb);
        cp16(bB + row * 144 + cb, gB + (size_t)row * 1024 + cb);
    }
}

__global__ __launch_bounds__(256, 2) void gemm_kernel(float* __restrict__ out) {
    extern __shared__ __align__(16) char smem[];
    uint32_t sbase;
    asm("{ .reg .u64 t; cvta.to.shared.u64 t, %1; cvt.u32.u64 %0, t; }"
        : "=r"(sbase) : "l"(smem));

    const int tid  = threadIdx.x;
    const int lane = tid & 31;
    const int warp = tid >> 5;
    const int wm = warp & 3;   // 4 warps in M
    const int wn = warp >> 2;  // 2 warps in N
    const int m0 = blockIdx.y * 128;
    const int n0 = blockIdx.x * 128;

    float* sXsq = reinterpret_cast<float*>(smem + OFF_SQ);
    float* sWsq = sXsq + 128;
    if (tid < 128) {
        sXsq[tid] = g_xsq[m0 + tid];
        sWsq[tid] = g_wsq[n0 + tid];
    }

    float acc[2][8][4];
#pragma unroll
    for (int mi = 0; mi < 2; mi++)
#pragma unroll
        for (int ni = 0; ni < 8; ni++)
#pragma unroll
            for (int e = 0; e < 4; e++) acc[mi][ni][e] = 0.0f;

    // lane-dependent ldmatrix address parts
    const int a_row = (lane & 15);
    const int a_cg  = (lane >> 4) << 3;
    const int b_r   = lane & 7;
    const int b_sel = lane >> 3;
    const int b_nof = ((b_sel >> 1) << 3) + b_r;
    const int b_kof = (b_sel & 1) << 3;

    // Prologue: stages 0 and 1 in flight
    load_stage(sbase, 0, 0, m0, n0, tid);
    asm volatile("cp.async.commit_group;" ::: "memory");
    load_stage(sbase, 1, 1, m0, n0, tid);
    asm volatile("cp.async.commit_group;" ::: "memory");

#pragma unroll 1
    for (int kc = 0; kc < 8; kc++) {
        const int st = kc % NSTAGE;
        if (kc < 7) asm volatile("cp.async.wait_group 1;" ::: "memory");
        else        asm volatile("cp.async.wait_group 0;" ::: "memory");
        __syncthreads();

        // issue loads for kc+2 into buffer (kc+2)%3 (last read at iter kc-1)
        if (kc + 2 < 8) {
            load_stage(sbase, (kc + 2) % NSTAGE, kc + 2, m0, n0, tid);
            asm volatile("cp.async.commit_group;" ::: "memory");
        }

        uint32_t aBase = sbase + st * STAGE_BYTES;
        uint32_t bBase = aBase + TILE_BYTES;

#pragma unroll
        for (int ks = 0; ks < 64; ks += 16) {
            uint32_t af[2][4];
#pragma unroll
            for (int mi = 0; mi < 2; mi++) {
                int r = wm * 32 + mi * 16 + a_row;
                int c = ks + a_cg;
                ldmatrix_x4(af[mi][0], af[mi][1], af[mi][2], af[mi][3],
                            aBase + r * 144 + c * 2);
            }
            uint32_t bfr[4][4];
#pragma unroll
            for (int j = 0; j < 4; j++) {
                int n = wn * 64 + j * 16 + b_nof;
                int c = ks + b_kof;
                ldmatrix_x4(bfr[j][0], bfr[j][1], bfr[j][2], bfr[j][3],
                            bBase + n * 144 + c * 2);
            }
#pragma unroll
            for (int mi = 0; mi < 2; mi++)
#pragma unroll
                for (int ni = 0; ni < 8; ni++) {
                    int j = ni >> 1, h = (ni & 1) * 2;
                    mma_bf16(acc[mi][ni], af[mi], bfr[j][h], bfr[j][h + 1]);
                }
        }
    }

    // Fused epilogue: q_un = 1/(1+max(dist,0))
    const int qt = lane >> 2;
    const int qr = lane & 3;
#pragma unroll
    for (int mi = 0; mi < 2; mi++) {
        int lr = wm * 32 + mi * 16 + qt;
        float xs0 = sXsq[lr];
        float xs1 = sXsq[lr + 8];
        int gr0 = (m0 + lr) * KOUT;
        int gr1 = gr0 + 8 * KOUT;
#pragma unroll
        for (int ni = 0; ni < 8; ni++) {
            int nl = wn * 64 + ni * 8 + qr * 2;
            float w0 = sWsq[nl];
            float w1 = sWsq[nl + 1];
            const float* d = acc[mi][ni];
            float q00 = 1.0f / (1.0f + fmaxf(xs0 + w0 - 2.0f * d[0], 0.0f));
            float q01 = 1.0f / (1.0f + fmaxf(xs0 + w1 - 2.0f * d[1], 0.0f));
            float q10 = 1.0f / (1.0f + fmaxf(xs1 + w0 - 2.0f * d[2], 0.0f));
            float q11 = 1.0f / (1.0f + fmaxf(xs1 + w1 - 2.0f * d[3], 0.0f));
            *reinterpret_cast<float2*>(&out[gr0 + n0 + nl]) = make_float2(q00, q01);
            *reinterpret_cast<float2*>(&out[gr1 + n0 + nl]) = make_float2(q10, q11);
        }
    }
}

// ---------------------------------------------------------------------------
// Kernel 3: deterministic row normalization (warp per row, L2-hot readback).
// ---------------------------------------------------------------------------
__global__ void norm_kernel(float* __restrict__ out) {
    int warp = threadIdx.x >> 5;
    int lane = threadIdx.x & 31;
    int row  = blockIdx.x * 8 + warp;
    float* p = out + (size_t)row * KOUT;

    float4 v[8];
    float s = 0.0f;
#pragma unroll
    for (int i = 0; i < 8; i++) {
        v[i] = *reinterpret_cast<float4*>(&p[i * 128 + lane * 4]);
        s += v[i].x + v[i].y + v[i].z + v[i].w;
    }
#pragma unroll
    for (int off = 16; off >= 1; off >>= 1)
        s += __shfl_xor_sync(0xFFFFFFFFu, s, off);
    float inv = 1.0f / s;
#pragma unroll
    for (int i = 0; i < 8; i++) {
        v[i].x *= inv; v[i].y *= inv; v[i].z *= inv; v[i].w *= inv;
        *reinterpret_cast<float4*>(&p[i * 128 + lane * 4]) = v[i];
    }
}

// ---------------------------------------------------------------------------
extern "C" void kernel_launch(void* const* d_in, const int* in_sizes, int n_in,
                              void* d_out, int out_size) {
    const float* x = (const float*)d_in[0];   // [8192, 512] f32
    const float* w = (const float*)d_in[1];   // [1024, 512] f32
    float* out = (float*)d_out;               // [8192, 1024] f32

    cudaFuncSetAttribute(gemm_kernel, cudaFuncAttributeMaxDynamicSharedMemorySize,
                         GEMM_SMEM);

    // 9216 rows, 4 rows per warp, 8 warps per 256-thread block -> 288 blocks
    prep_kernel<<<288, 256>>>(x, w);
    gemm_kernel<<<dim3(KOUT / 128, B_ROWS / 128), 256, GEMM_SMEM>>>(out);
    norm_kernel<<<B_ROWS / 8, 256>>>(out);
}